// round 1
// baseline (speedup 1.0000x reference)
#include <cuda_runtime.h>
#include <math.h>

#define HIDDEN 2560
#define NH 32
#define NKV 8
#define HD 80
#define BATCH 2
#define SEQ 2048
#define M_TOK (BATCH * SEQ)   // 4096

// ---------------- scratch (static device globals; no runtime alloc) ----------
__device__ float g_q[M_TOK * NH * HD];    // 4096 x 2560
__device__ float g_k[M_TOK * NKV * HD];   // 4096 x 640
__device__ float g_v[M_TOK * NKV * HD];   // 4096 x 640
__device__ float g_o[M_TOK * NH * HD];    // 4096 x 2560

// ---------------- SGEMM: C[M,N] = A[M,K] @ B[K,N], all row-major, fp32 -------
// BM=BN=128, BK=16, 256 threads, 8x8 per thread. All dims divisible by tiles
// for our shapes (M=4096, N in {2560,640}, K=2560).
#define BM 128
#define BN 128
#define BK 16
#define TM 8
#define TN 8

__global__ __launch_bounds__(256) void sgemm_kernel(
    const float* __restrict__ A, const float* __restrict__ B,
    float* __restrict__ C, int M, int N, int K)
{
    __shared__ float As[BK][BM];   // A tile transposed
    __shared__ float Bs[BK][BN];

    const int tid = threadIdx.x;
    const int bm = blockIdx.y * BM;
    const int bn = blockIdx.x * BN;
    const int ty = tid >> 4;        // 0..15
    const int tx = tid & 15;        // 0..15

    const int arow0 = tid >> 2;          // 0..63
    const int ac4   = (tid & 3) * 4;     // 0,4,8,12
    const int brow0 = tid >> 5;          // 0..7
    const int bc4   = (tid & 31) * 4;    // 0..124

    float acc[TM][TN];
    #pragma unroll
    for (int i = 0; i < TM; i++)
        #pragma unroll
        for (int j = 0; j < TN; j++) acc[i][j] = 0.f;

    for (int k0 = 0; k0 < K; k0 += BK) {
        // load A tile (transposed into As)
        #pragma unroll
        for (int i = 0; i < 2; i++) {
            int row = arow0 + i * 64;
            float4 a = *(const float4*)(A + (size_t)(bm + row) * K + k0 + ac4);
            As[ac4 + 0][row] = a.x;
            As[ac4 + 1][row] = a.y;
            As[ac4 + 2][row] = a.z;
            As[ac4 + 3][row] = a.w;
        }
        // load B tile
        #pragma unroll
        for (int i = 0; i < 2; i++) {
            int r = brow0 + i * 8;
            *(float4*)(&Bs[r][bc4]) =
                *(const float4*)(B + (size_t)(k0 + r) * N + bn + bc4);
        }
        __syncthreads();

        #pragma unroll
        for (int kk = 0; kk < BK; kk++) {
            float a[TM], b[TN];
            *(float4*)(a)     = *(const float4*)(&As[kk][ty * TM]);
            *(float4*)(a + 4) = *(const float4*)(&As[kk][ty * TM + 4]);
            *(float4*)(b)     = *(const float4*)(&Bs[kk][tx * TN]);
            *(float4*)(b + 4) = *(const float4*)(&Bs[kk][tx * TN + 4]);
            #pragma unroll
            for (int i = 0; i < TM; i++)
                #pragma unroll
                for (int j = 0; j < TN; j++)
                    acc[i][j] += a[i] * b[j];
        }
        __syncthreads();
    }

    #pragma unroll
    for (int i = 0; i < TM; i++) {
        float* cp = C + (size_t)(bm + ty * TM + i) * N + bn + tx * TN;
        *(float4*)(cp)     = make_float4(acc[i][0], acc[i][1], acc[i][2], acc[i][3]);
        *(float4*)(cp + 4) = make_float4(acc[i][4], acc[i][5], acc[i][6], acc[i][7]);
    }
}

// ---------------- RoPE (in-place over q or k buffer) -------------------------
// t: [M_TOK, nheads*HD]; one thread per (token, head, pair i<HD/2)
__global__ void rope_kernel(float* __restrict__ t,
                            const float* __restrict__ cosf,
                            const float* __restrict__ sinf,
                            int nheads, int total)
{
    int idx = blockIdx.x * blockDim.x + threadIdx.x;
    if (idx >= total) return;
    int i   = idx % (HD / 2);
    int h   = (idx / (HD / 2)) % nheads;
    int tok = idx / ((HD / 2) * nheads);
    int s   = tok % SEQ;

    float* p = t + (size_t)tok * nheads * HD + h * HD;
    float x1 = p[i];
    float x2 = p[i + HD / 2];
    float c1 = cosf[s * HD + i];
    float s1 = sinf[s * HD + i];
    float c2 = cosf[s * HD + i + HD / 2];
    float s2 = sinf[s * HD + i + HD / 2];
    p[i]          = x1 * c1 - x2 * s1;
    p[i + HD / 2] = x2 * c2 + x1 * s2;
}

// ---------------- Flash-style causal GQA attention ---------------------------
// Block: 256 threads. 128 q rows per block; thread pair (2*r, 2*r+1) splits
// HD=80 into two halves of 40. K/V tiles of 64 keys staged in smem.
#define KT 64
#define QT 128

__global__ __launch_bounds__(256) void attn_kernel(
    const float* __restrict__ q, const float* __restrict__ k,
    const float* __restrict__ v, float* __restrict__ o)
{
    __shared__ float Ks[KT][HD];
    __shared__ float Vs[KT][HD];

    const int b   = blockIdx.z;
    const int h   = blockIdx.y;
    const int qt  = blockIdx.x;
    const int kvh = h >> 2;               // 32 heads -> 8 kv heads, group 4
    const int tid = threadIdx.x;
    const int qrow = tid >> 1;            // 0..127
    const int half = tid & 1;             // which 40-dim half
    const int qpos = qt * QT + qrow;
    const float scale = rsqrtf((float)HD);

    // load q row half into registers
    float qr[40];
    const float* qp = q + ((size_t)(b * SEQ) + qpos) * (NH * HD) + h * HD + half * 40;
    #pragma unroll
    for (int i = 0; i < 10; i++)
        *(float4*)(qr + 4 * i) = *(const float4*)(qp + 4 * i);

    float oacc[40];
    #pragma unroll
    for (int i = 0; i < 40; i++) oacc[i] = 0.f;
    float m = -INFINITY;
    float l = 0.f;

    const int ktiles = qt * (QT / KT) + (QT / KT);  // cover keys up to qt*128+127
    for (int t = 0; t < ktiles; t++) {
        const int k0 = t * KT;
        // cooperative load of K and V tiles: 64*80 floats = 1280 float4, 5/thread
        #pragma unroll
        for (int i = 0; i < 5; i++) {
            int f  = tid + i * 256;          // 0..1279
            int j  = f / 20;
            int d4 = (f % 20) * 4;
            size_t g = ((size_t)(b * SEQ) + k0 + j) * (NKV * HD) + kvh * HD + d4;
            *(float4*)(&Ks[j][d4]) = *(const float4*)(k + g);
            *(float4*)(&Vs[j][d4]) = *(const float4*)(v + g);
        }
        __syncthreads();

        #pragma unroll 1
        for (int j0 = 0; j0 < KT; j0 += 16) {
            float s[16];
            float cm = -1e30f;
            #pragma unroll
            for (int jj = 0; jj < 16; jj++) {
                int j = j0 + jj;
                float part = 0.f;
                #pragma unroll
                for (int d4 = 0; d4 < 10; d4++) {
                    float4 k4 = *(const float4*)(&Ks[j][half * 40 + d4 * 4]);
                    part += qr[d4 * 4 + 0] * k4.x;
                    part += qr[d4 * 4 + 1] * k4.y;
                    part += qr[d4 * 4 + 2] * k4.z;
                    part += qr[d4 * 4 + 3] * k4.w;
                }
                part += __shfl_xor_sync(0xffffffffu, part, 1);
                float sc = part * scale;
                if (k0 + j > qpos) sc = -1e30f;   // causal mask
                s[jj] = sc;
                cm = fmaxf(cm, sc);
            }
            float mnew  = fmaxf(m, cm);
            float alpha = __expf(m - mnew);   // exp(-inf)=0 on first chunk
            m = mnew;
            l *= alpha;
            #pragma unroll
            for (int i = 0; i < 40; i++) oacc[i] *= alpha;
            #pragma unroll
            for (int jj = 0; jj < 16; jj++) {
                float p = __expf(s[jj] - mnew);
                l += p;
                #pragma unroll
                for (int d4 = 0; d4 < 10; d4++) {
                    float4 v4 = *(const float4*)(&Vs[j0 + jj][half * 40 + d4 * 4]);
                    oacc[d4 * 4 + 0] += p * v4.x;
                    oacc[d4 * 4 + 1] += p * v4.y;
                    oacc[d4 * 4 + 2] += p * v4.z;
                    oacc[d4 * 4 + 3] += p * v4.w;
                }
            }
        }
        __syncthreads();
    }

    const float inv = 1.0f / l;
    float* op = o + ((size_t)(b * SEQ) + qpos) * (NH * HD) + h * HD + half * 40;
    #pragma unroll
    for (int i = 0; i < 10; i++) {
        float4 r;
        r.x = oacc[4 * i + 0] * inv;
        r.y = oacc[4 * i + 1] * inv;
        r.z = oacc[4 * i + 2] * inv;
        r.w = oacc[4 * i + 3] * inv;
        *(float4*)(op + 4 * i) = r;
    }
}

// ---------------- launch ------------------------------------------------------
extern "C" void kernel_launch(void* const* d_in, const int* in_sizes, int n_in,
                              void* d_out, int out_size)
{
    const float* x    = (const float*)d_in[0];
    const float* cosf = (const float*)d_in[1];
    const float* sinf = (const float*)d_in[2];
    const float* Wq   = (const float*)d_in[3];
    const float* Wk   = (const float*)d_in[4];
    const float* Wv   = (const float*)d_in[5];
    const float* Wo   = (const float*)d_in[6];
    float* out = (float*)d_out;

    float *qb, *kb, *vb, *ob;
    cudaGetSymbolAddress((void**)&qb, g_q);
    cudaGetSymbolAddress((void**)&kb, g_k);
    cudaGetSymbolAddress((void**)&vb, g_v);
    cudaGetSymbolAddress((void**)&ob, g_o);

    // QKV projections
    {
        dim3 gq(HIDDEN / BN, M_TOK / BM);       // 20 x 32
        sgemm_kernel<<<gq, 256>>>(x, Wq, qb, M_TOK, NH * HD, HIDDEN);
        dim3 gk((NKV * HD) / BN, M_TOK / BM);   // 5 x 32
        sgemm_kernel<<<gk, 256>>>(x, Wk, kb, M_TOK, NKV * HD, HIDDEN);
        sgemm_kernel<<<gk, 256>>>(x, Wv, vb, M_TOK, NKV * HD, HIDDEN);
    }

    // RoPE on q and k
    {
        int tq = M_TOK * NH * (HD / 2);
        rope_kernel<<<(tq + 255) / 256, 256>>>(qb, cosf, sinf, NH, tq);
        int tk = M_TOK * NKV * (HD / 2);
        rope_kernel<<<(tk + 255) / 256, 256>>>(kb, cosf, sinf, NKV, tk);
    }

    // attention
    {
        dim3 ga(SEQ / QT, NH, BATCH);           // 16 x 32 x 2
        attn_kernel<<<ga, 256>>>(qb, kb, vb, ob);
    }

    // output projection
    {
        dim3 go(HIDDEN / BN, M_TOK / BM);       // 20 x 32
        sgemm_kernel<<<go, 256>>>(ob, Wo, out, M_TOK, HIDDEN, HIDDEN);
    }
}

// round 2
// speedup vs baseline: 1.7937x; 1.7937x over previous
#include <cuda_runtime.h>
#include <math.h>

#define HIDDEN 2560
#define NH 32
#define NKV 8
#define HD 80
#define BATCH 2
#define SEQ 2048
#define M_TOK (BATCH * SEQ)   // 4096

// ---------------- scratch (static device globals; no runtime alloc) ----------
__device__ float g_q[M_TOK * NH * HD];    // 4096 x 2560
__device__ float g_k[M_TOK * NKV * HD];   // 4096 x 640
__device__ float g_v[M_TOK * NKV * HD];   // 4096 x 640
__device__ float g_o[M_TOK * NH * HD];    // 4096 x 2560

// ---------------- TF32 tensor-core GEMM --------------------------------------
// C[M,N] = A[M,K] @ B[K,N], row-major fp32 in/out, tf32 mma.sync compute.
// Block tile 128x128, BK=32, 256 threads (8 warps in 4x2), warp tile 32x64.
// Requires M%128==0, N%128==0, K%32==0 (true for all four GEMMs here).

__device__ __forceinline__ unsigned f2tf32(float x) {
    unsigned y;
    asm("cvt.rna.tf32.f32 %0, %1;" : "=r"(y) : "f"(x));
    return y;
}

#define GBM 128
#define GBN 128
#define GBK 32
#define APAD 4      // A row length 36 floats
#define BPAD 8      // B row length 136 floats

__global__ __launch_bounds__(256) void tf32_gemm_kernel(
    const float* __restrict__ A, const float* __restrict__ B,
    float* __restrict__ C, int M, int N, int K)
{
    __shared__ unsigned As[GBM][GBK + APAD];   // [m][k], tf32 bits
    __shared__ unsigned Bs[GBK][GBN + BPAD];   // [k][n], tf32 bits

    const int tid  = threadIdx.x;
    const int lane = tid & 31;
    const int warp = tid >> 5;
    const int wm   = (warp & 3) * 32;   // warp M offset in block tile
    const int wn   = (warp >> 2) * 64;  // warp N offset in block tile
    const int bm   = blockIdx.y * GBM;
    const int bn   = blockIdx.x * GBN;

    const int lq = lane >> 2;   // 0..7
    const int lr = lane & 3;    // 0..3

    float acc[2][8][4];
    #pragma unroll
    for (int i = 0; i < 2; i++)
        #pragma unroll
        for (int j = 0; j < 8; j++)
            #pragma unroll
            for (int r = 0; r < 4; r++) acc[i][j][r] = 0.f;

    for (int k0 = 0; k0 < K; k0 += GBK) {
        // ---- load A tile 128x32 (1024 float4, 4 per thread) ----
        #pragma unroll
        for (int i = 0; i < 4; i++) {
            int idx  = tid + i * 256;           // 0..1023
            int row  = idx >> 3;                // 0..127
            int col4 = (idx & 7) * 4;           // 0..28
            float4 a = *(const float4*)(A + (size_t)(bm + row) * K + k0 + col4);
            As[row][col4 + 0] = f2tf32(a.x);
            As[row][col4 + 1] = f2tf32(a.y);
            As[row][col4 + 2] = f2tf32(a.z);
            As[row][col4 + 3] = f2tf32(a.w);
        }
        // ---- load B tile 32x128 (1024 float4, 4 per thread) ----
        #pragma unroll
        for (int i = 0; i < 4; i++) {
            int idx  = tid + i * 256;
            int row  = idx >> 5;                // 0..31
            int col4 = (idx & 31) * 4;          // 0..124
            float4 b = *(const float4*)(B + (size_t)(k0 + row) * N + bn + col4);
            Bs[row][col4 + 0] = f2tf32(b.x);
            Bs[row][col4 + 1] = f2tf32(b.y);
            Bs[row][col4 + 2] = f2tf32(b.z);
            Bs[row][col4 + 3] = f2tf32(b.w);
        }
        __syncthreads();

        // ---- 4 k-steps of m16n8k8 ----
        #pragma unroll
        for (int ks = 0; ks < GBK; ks += 8) {
            unsigned af[2][4];
            #pragma unroll
            for (int mi = 0; mi < 2; mi++) {
                int m = wm + mi * 16 + lq;
                af[mi][0] = As[m    ][ks + lr];
                af[mi][1] = As[m + 8][ks + lr];
                af[mi][2] = As[m    ][ks + 4 + lr];
                af[mi][3] = As[m + 8][ks + 4 + lr];
            }
            unsigned bf[8][2];
            #pragma unroll
            for (int ni = 0; ni < 8; ni++) {
                int n = wn + ni * 8 + lq;
                bf[ni][0] = Bs[ks + lr    ][n];
                bf[ni][1] = Bs[ks + lr + 4][n];
            }
            #pragma unroll
            for (int mi = 0; mi < 2; mi++)
                #pragma unroll
                for (int ni = 0; ni < 8; ni++) {
                    asm volatile(
                        "mma.sync.aligned.m16n8k8.row.col.f32.tf32.tf32.f32 "
                        "{%0,%1,%2,%3}, {%4,%5,%6,%7}, {%8,%9}, {%0,%1,%2,%3};"
                        : "+f"(acc[mi][ni][0]), "+f"(acc[mi][ni][1]),
                          "+f"(acc[mi][ni][2]), "+f"(acc[mi][ni][3])
                        : "r"(af[mi][0]), "r"(af[mi][1]),
                          "r"(af[mi][2]), "r"(af[mi][3]),
                          "r"(bf[ni][0]), "r"(bf[ni][1]));
                }
        }
        __syncthreads();
    }

    // ---- epilogue: c0/c1 at (row, 2*lr), c2/c3 at (row+8, 2*lr) ----
    #pragma unroll
    for (int mi = 0; mi < 2; mi++) {
        int m = bm + wm + mi * 16 + lq;
        #pragma unroll
        for (int ni = 0; ni < 8; ni++) {
            int n = bn + wn + ni * 8 + lr * 2;
            float2* p0 = (float2*)(C + (size_t)m * N + n);
            float2* p1 = (float2*)(C + (size_t)(m + 8) * N + n);
            *p0 = make_float2(acc[mi][ni][0], acc[mi][ni][1]);
            *p1 = make_float2(acc[mi][ni][2], acc[mi][ni][3]);
        }
    }
}

// ---------------- RoPE (in-place over q or k buffer) -------------------------
__global__ void rope_kernel(float* __restrict__ t,
                            const float* __restrict__ cosf,
                            const float* __restrict__ sinf,
                            int nheads, int total)
{
    int idx = blockIdx.x * blockDim.x + threadIdx.x;
    if (idx >= total) return;
    int i   = idx % (HD / 2);
    int h   = (idx / (HD / 2)) % nheads;
    int tok = idx / ((HD / 2) * nheads);
    int s   = tok % SEQ;

    float* p = t + (size_t)tok * nheads * HD + h * HD;
    float x1 = p[i];
    float x2 = p[i + HD / 2];
    float c1 = cosf[s * HD + i];
    float s1 = sinf[s * HD + i];
    float c2 = cosf[s * HD + i + HD / 2];
    float s2 = sinf[s * HD + i + HD / 2];
    p[i]          = x1 * c1 - x2 * s1;
    p[i + HD / 2] = x2 * c2 + x1 * s2;
}

// ---------------- Flash-style causal GQA attention ---------------------------
#define KT 64
#define QT 128

__global__ __launch_bounds__(256) void attn_kernel(
    const float* __restrict__ q, const float* __restrict__ k,
    const float* __restrict__ v, float* __restrict__ o)
{
    __shared__ float Ks[KT][HD];
    __shared__ float Vs[KT][HD];

    const int b   = blockIdx.z;
    const int h   = blockIdx.y;
    const int qt  = blockIdx.x;
    const int kvh = h >> 2;
    const int tid = threadIdx.x;
    const int qrow = tid >> 1;
    const int half = tid & 1;
    const int qpos = qt * QT + qrow;
    const float scale = rsqrtf((float)HD);

    float qr[40];
    const float* qp = q + ((size_t)(b * SEQ) + qpos) * (NH * HD) + h * HD + half * 40;
    #pragma unroll
    for (int i = 0; i < 10; i++)
        *(float4*)(qr + 4 * i) = *(const float4*)(qp + 4 * i);

    float oacc[40];
    #pragma unroll
    for (int i = 0; i < 40; i++) oacc[i] = 0.f;
    float m = -INFINITY;
    float l = 0.f;

    const int ktiles = qt * (QT / KT) + (QT / KT);
    for (int t = 0; t < ktiles; t++) {
        const int k0 = t * KT;
        #pragma unroll
        for (int i = 0; i < 5; i++) {
            int f  = tid + i * 256;
            int j  = f / 20;
            int d4 = (f % 20) * 4;
            size_t g = ((size_t)(b * SEQ) + k0 + j) * (NKV * HD) + kvh * HD + d4;
            *(float4*)(&Ks[j][d4]) = *(const float4*)(k + g);
            *(float4*)(&Vs[j][d4]) = *(const float4*)(v + g);
        }
        __syncthreads();

        #pragma unroll 1
        for (int j0 = 0; j0 < KT; j0 += 16) {
            float s[16];
            float cm = -1e30f;
            #pragma unroll
            for (int jj = 0; jj < 16; jj++) {
                int j = j0 + jj;
                float part = 0.f;
                #pragma unroll
                for (int d4 = 0; d4 < 10; d4++) {
                    float4 k4 = *(const float4*)(&Ks[j][half * 40 + d4 * 4]);
                    part += qr[d4 * 4 + 0] * k4.x;
                    part += qr[d4 * 4 + 1] * k4.y;
                    part += qr[d4 * 4 + 2] * k4.z;
                    part += qr[d4 * 4 + 3] * k4.w;
                }
                part += __shfl_xor_sync(0xffffffffu, part, 1);
                float sc = part * scale;
                if (k0 + j > qpos) sc = -1e30f;
                s[jj] = sc;
                cm = fmaxf(cm, sc);
            }
            float mnew  = fmaxf(m, cm);
            float alpha = __expf(m - mnew);
            m = mnew;
            l *= alpha;
            #pragma unroll
            for (int i = 0; i < 40; i++) oacc[i] *= alpha;
            #pragma unroll
            for (int jj = 0; jj < 16; jj++) {
                float p = __expf(s[jj] - mnew);
                l += p;
                #pragma unroll
                for (int d4 = 0; d4 < 10; d4++) {
                    float4 v4 = *(const float4*)(&Vs[j0 + jj][half * 40 + d4 * 4]);
                    oacc[d4 * 4 + 0] += p * v4.x;
                    oacc[d4 * 4 + 1] += p * v4.y;
                    oacc[d4 * 4 + 2] += p * v4.z;
                    oacc[d4 * 4 + 3] += p * v4.w;
                }
            }
        }
        __syncthreads();
    }

    const float inv = 1.0f / l;
    float* op = o + ((size_t)(b * SEQ) + qpos) * (NH * HD) + h * HD + half * 40;
    #pragma unroll
    for (int i = 0; i < 10; i++) {
        float4 r;
        r.x = oacc[4 * i + 0] * inv;
        r.y = oacc[4 * i + 1] * inv;
        r.z = oacc[4 * i + 2] * inv;
        r.w = oacc[4 * i + 3] * inv;
        *(float4*)(op + 4 * i) = r;
    }
}

// ---------------- launch ------------------------------------------------------
extern "C" void kernel_launch(void* const* d_in, const int* in_sizes, int n_in,
                              void* d_out, int out_size)
{
    const float* x    = (const float*)d_in[0];
    const float* cosf = (const float*)d_in[1];
    const float* sinf = (const float*)d_in[2];
    const float* Wq   = (const float*)d_in[3];
    const float* Wk   = (const float*)d_in[4];
    const float* Wv   = (const float*)d_in[5];
    const float* Wo   = (const float*)d_in[6];
    float* out = (float*)d_out;

    float *qb, *kb, *vb, *ob;
    cudaGetSymbolAddress((void**)&qb, g_q);
    cudaGetSymbolAddress((void**)&kb, g_k);
    cudaGetSymbolAddress((void**)&vb, g_v);
    cudaGetSymbolAddress((void**)&ob, g_o);

    // QKV projections (tf32 tensor cores)
    {
        dim3 gq(HIDDEN / GBN, M_TOK / GBM);       // 20 x 32
        tf32_gemm_kernel<<<gq, 256>>>(x, Wq, qb, M_TOK, NH * HD, HIDDEN);
        dim3 gk((NKV * HD) / GBN, M_TOK / GBM);   // 5 x 32
        tf32_gemm_kernel<<<gk, 256>>>(x, Wk, kb, M_TOK, NKV * HD, HIDDEN);
        tf32_gemm_kernel<<<gk, 256>>>(x, Wv, vb, M_TOK, NKV * HD, HIDDEN);
    }

    // RoPE on q and k
    {
        int tq = M_TOK * NH * (HD / 2);
        rope_kernel<<<(tq + 255) / 256, 256>>>(qb, cosf, sinf, NH, tq);
        int tk = M_TOK * NKV * (HD / 2);
        rope_kernel<<<(tk + 255) / 256, 256>>>(kb, cosf, sinf, NKV, tk);
    }

    // attention (fp32 flash)
    {
        dim3 ga(SEQ / QT, NH, BATCH);
        attn_kernel<<<ga, 256>>>(qb, kb, vb, ob);
    }

    // output projection (tf32 tensor cores)
    {
        dim3 go(HIDDEN / GBN, M_TOK / GBM);
        tf32_gemm_kernel<<<go, 256>>>(ob, Wo, out, M_TOK, HIDDEN, HIDDEN);
    }
}

// round 3
// speedup vs baseline: 3.2734x; 1.8249x over previous
#include <cuda_runtime.h>
#include <math.h>

#define HIDDEN 2560
#define NH 32
#define NKV 8
#define HD 80
#define BATCH 2
#define SEQ 2048
#define M_TOK (BATCH * SEQ)   // 4096

// ---------------- scratch (static device globals; no runtime alloc) ----------
__device__ float g_q[M_TOK * NH * HD];    // 4096 x 2560
__device__ float g_k[M_TOK * NKV * HD];   // 4096 x 640
__device__ float g_v[M_TOK * NKV * HD];   // 4096 x 640
__device__ float g_o[M_TOK * NH * HD];    // 4096 x 2560

__device__ __forceinline__ unsigned f2tf32(float x) {
    unsigned y;
    asm("cvt.rna.tf32.f32 %0, %1;" : "=r"(y) : "f"(x));
    return y;
}

__device__ __forceinline__ void mma_tf32(float* c, const unsigned* a,
                                         unsigned b0, unsigned b1) {
    asm volatile(
        "mma.sync.aligned.m16n8k8.row.col.f32.tf32.tf32.f32 "
        "{%0,%1,%2,%3}, {%4,%5,%6,%7}, {%8,%9}, {%0,%1,%2,%3};"
        : "+f"(c[0]), "+f"(c[1]), "+f"(c[2]), "+f"(c[3])
        : "r"(a[0]), "r"(a[1]), "r"(a[2]), "r"(a[3]),
          "r"(b0), "r"(b1));
}

// ---------------- TF32 tensor-core GEMM (unchanged from R2) ------------------
#define GBM 128
#define GBN 128
#define GBK 32
#define APAD 4
#define BPAD 8

__global__ __launch_bounds__(256) void tf32_gemm_kernel(
    const float* __restrict__ A, const float* __restrict__ B,
    float* __restrict__ C, int M, int N, int K)
{
    __shared__ unsigned As[GBM][GBK + APAD];
    __shared__ unsigned Bs[GBK][GBN + BPAD];

    const int tid  = threadIdx.x;
    const int lane = tid & 31;
    const int warp = tid >> 5;
    const int wm   = (warp & 3) * 32;
    const int wn   = (warp >> 2) * 64;
    const int bm   = blockIdx.y * GBM;
    const int bn   = blockIdx.x * GBN;

    const int lq = lane >> 2;
    const int lr = lane & 3;

    float acc[2][8][4];
    #pragma unroll
    for (int i = 0; i < 2; i++)
        #pragma unroll
        for (int j = 0; j < 8; j++)
            #pragma unroll
            for (int r = 0; r < 4; r++) acc[i][j][r] = 0.f;

    for (int k0 = 0; k0 < K; k0 += GBK) {
        #pragma unroll
        for (int i = 0; i < 4; i++) {
            int idx  = tid + i * 256;
            int row  = idx >> 3;
            int col4 = (idx & 7) * 4;
            float4 a = *(const float4*)(A + (size_t)(bm + row) * K + k0 + col4);
            As[row][col4 + 0] = f2tf32(a.x);
            As[row][col4 + 1] = f2tf32(a.y);
            As[row][col4 + 2] = f2tf32(a.z);
            As[row][col4 + 3] = f2tf32(a.w);
        }
        #pragma unroll
        for (int i = 0; i < 4; i++) {
            int idx  = tid + i * 256;
            int row  = idx >> 5;
            int col4 = (idx & 31) * 4;
            float4 b = *(const float4*)(B + (size_t)(k0 + row) * N + bn + col4);
            Bs[row][col4 + 0] = f2tf32(b.x);
            Bs[row][col4 + 1] = f2tf32(b.y);
            Bs[row][col4 + 2] = f2tf32(b.z);
            Bs[row][col4 + 3] = f2tf32(b.w);
        }
        __syncthreads();

        #pragma unroll
        for (int ks = 0; ks < GBK; ks += 8) {
            unsigned af[2][4];
            #pragma unroll
            for (int mi = 0; mi < 2; mi++) {
                int m = wm + mi * 16 + lq;
                af[mi][0] = As[m    ][ks + lr];
                af[mi][1] = As[m + 8][ks + lr];
                af[mi][2] = As[m    ][ks + 4 + lr];
                af[mi][3] = As[m + 8][ks + 4 + lr];
            }
            unsigned bf[8][2];
            #pragma unroll
            for (int ni = 0; ni < 8; ni++) {
                int n = wn + ni * 8 + lq;
                bf[ni][0] = Bs[ks + lr    ][n];
                bf[ni][1] = Bs[ks + lr + 4][n];
            }
            #pragma unroll
            for (int mi = 0; mi < 2; mi++)
                #pragma unroll
                for (int ni = 0; ni < 8; ni++)
                    mma_tf32(acc[mi][ni], af[mi], bf[ni][0], bf[ni][1]);
        }
        __syncthreads();
    }

    #pragma unroll
    for (int mi = 0; mi < 2; mi++) {
        int m = bm + wm + mi * 16 + lq;
        #pragma unroll
        for (int ni = 0; ni < 8; ni++) {
            int n = bn + wn + ni * 8 + lr * 2;
            float2* p0 = (float2*)(C + (size_t)m * N + n);
            float2* p1 = (float2*)(C + (size_t)(m + 8) * N + n);
            *p0 = make_float2(acc[mi][ni][0], acc[mi][ni][1]);
            *p1 = make_float2(acc[mi][ni][2], acc[mi][ni][3]);
        }
    }
}

// ---------------- RoPE (unchanged) --------------------------------------------
__global__ void rope_kernel(float* __restrict__ t,
                            const float* __restrict__ cosf,
                            const float* __restrict__ sinf,
                            int nheads, int total)
{
    int idx = blockIdx.x * blockDim.x + threadIdx.x;
    if (idx >= total) return;
    int i   = idx % (HD / 2);
    int h   = (idx / (HD / 2)) % nheads;
    int tok = idx / ((HD / 2) * nheads);
    int s   = tok % SEQ;

    float* p = t + (size_t)tok * nheads * HD + h * HD;
    float x1 = p[i];
    float x2 = p[i + HD / 2];
    float c1 = cosf[s * HD + i];
    float s1 = sinf[s * HD + i];
    float c2 = cosf[s * HD + i + HD / 2];
    float s2 = sinf[s * HD + i + HD / 2];
    p[i]          = x1 * c1 - x2 * s1;
    p[i + HD / 2] = x2 * c2 + x1 * s2;
}

// ---------------- TF32 tensor-core flash attention ----------------------------
// One block = 128 q rows of one (b,h). 256 threads = 8 warps; warp w owns q rows
// [w*16, w*16+16). QK^T: warp tile 16x128 (16 n-frags, 10 k-steps over HD=80).
// Softmax rows live entirely in one warp -> shfl over 4-lane groups only.
// PV: P staged per-warp in smem (tf32), V staged transposed; 16 k-steps, 10 n-frags.
#define QSTR 84     // Q/K smem row stride (uints) — conflict-free fragment reads
#define PSTR 132    // P/Vt smem row stride

__global__ __launch_bounds__(256) void attn_tc_kernel(
    const float* __restrict__ q, const float* __restrict__ k,
    const float* __restrict__ v, float* __restrict__ o)
{
    extern __shared__ unsigned sm[];
    unsigned* Qs = sm;                       // [128][84]
    unsigned* Ks = Qs + 128 * QSTR;          // [128][84]
    unsigned* Vt = Ks + 128 * QSTR;          // [80][132]  (V transposed: [d][key])
    unsigned* Ps = Vt + 80 * PSTR;           // [128][132]

    const int b    = blockIdx.z;
    const int h    = blockIdx.y;
    const int qt   = blockIdx.x;
    const int kvh  = h >> 2;
    const int tid  = threadIdx.x;
    const int lane = tid & 31;
    const int warp = tid >> 5;
    const int lq   = lane >> 2;
    const int lr   = lane & 3;
    const int wr   = warp * 16;              // warp's q-row base in tile
    const float scale = rsqrtf((float)HD);

    // ---- load Q tile (128 x 80) as tf32 ----
    #pragma unroll
    for (int i = 0; i < 10; i++) {
        int f   = tid + i * 256;             // 0..2559
        int row = f / 20;
        int c4  = (f % 20) * 4;
        float4 a = *(const float4*)(q + ((size_t)(b * SEQ + qt * 128 + row)) * (NH * HD)
                                      + h * HD + c4);
        Qs[row * QSTR + c4 + 0] = f2tf32(a.x);
        Qs[row * QSTR + c4 + 1] = f2tf32(a.y);
        Qs[row * QSTR + c4 + 2] = f2tf32(a.z);
        Qs[row * QSTR + c4 + 3] = f2tf32(a.w);
    }

    float oacc[10][4];
    #pragma unroll
    for (int i = 0; i < 10; i++)
        #pragma unroll
        for (int j = 0; j < 4; j++) oacc[i][j] = 0.f;
    float m0 = -INFINITY, m1 = -INFINITY;
    float l0 = 0.f, l1 = 0.f;

    const int row0 = qt * 128 + wr + lq;
    const int row1 = row0 + 8;

    for (int kt = 0; kt <= qt; kt++) {
        __syncthreads();
        // ---- load K tile (128 x 80) and V^T (80 x 128) as tf32 ----
        #pragma unroll
        for (int i = 0; i < 10; i++) {
            int f   = tid + i * 256;
            int row = f / 20;
            int c4  = (f % 20) * 4;
            size_t g = ((size_t)(b * SEQ + kt * 128 + row)) * (NKV * HD) + kvh * HD + c4;
            float4 kk = *(const float4*)(k + g);
            Ks[row * QSTR + c4 + 0] = f2tf32(kk.x);
            Ks[row * QSTR + c4 + 1] = f2tf32(kk.y);
            Ks[row * QSTR + c4 + 2] = f2tf32(kk.z);
            Ks[row * QSTR + c4 + 3] = f2tf32(kk.w);
            float4 vv = *(const float4*)(v + g);
            Vt[(c4 + 0) * PSTR + row] = f2tf32(vv.x);
            Vt[(c4 + 1) * PSTR + row] = f2tf32(vv.y);
            Vt[(c4 + 2) * PSTR + row] = f2tf32(vv.z);
            Vt[(c4 + 3) * PSTR + row] = f2tf32(vv.w);
        }
        __syncthreads();

        // ---- QK^T: S[16 x 128] per warp ----
        float sc[16][4];
        #pragma unroll
        for (int ni = 0; ni < 16; ni++)
            #pragma unroll
            for (int j = 0; j < 4; j++) sc[ni][j] = 0.f;

        #pragma unroll
        for (int ks = 0; ks < 10; ks++) {
            unsigned af[4];
            af[0] = Qs[(wr + lq    ) * QSTR + ks * 8 + lr    ];
            af[1] = Qs[(wr + lq + 8) * QSTR + ks * 8 + lr    ];
            af[2] = Qs[(wr + lq    ) * QSTR + ks * 8 + 4 + lr];
            af[3] = Qs[(wr + lq + 8) * QSTR + ks * 8 + 4 + lr];
            #pragma unroll
            for (int ni = 0; ni < 16; ni++) {
                unsigned b0 = Ks[(ni * 8 + lq) * QSTR + ks * 8 + lr    ];
                unsigned b1 = Ks[(ni * 8 + lq) * QSTR + ks * 8 + 4 + lr];
                mma_tf32(sc[ni], af, b0, b1);
            }
        }

        // ---- scale + causal mask ----
        const bool diag = (kt == qt);
        #pragma unroll
        for (int ni = 0; ni < 16; ni++) {
            int c = kt * 128 + ni * 8 + lr * 2;
            sc[ni][0] = (diag && c     > row0) ? -1e30f : sc[ni][0] * scale;
            sc[ni][1] = (diag && c + 1 > row0) ? -1e30f : sc[ni][1] * scale;
            sc[ni][2] = (diag && c     > row1) ? -1e30f : sc[ni][2] * scale;
            sc[ni][3] = (diag && c + 1 > row1) ? -1e30f : sc[ni][3] * scale;
        }

        // ---- online softmax (rows row0, row1 per thread-group of 4 lanes) ----
        float rm0 = -1e30f, rm1 = -1e30f;
        #pragma unroll
        for (int ni = 0; ni < 16; ni++) {
            rm0 = fmaxf(rm0, fmaxf(sc[ni][0], sc[ni][1]));
            rm1 = fmaxf(rm1, fmaxf(sc[ni][2], sc[ni][3]));
        }
        rm0 = fmaxf(rm0, __shfl_xor_sync(0xffffffffu, rm0, 1));
        rm0 = fmaxf(rm0, __shfl_xor_sync(0xffffffffu, rm0, 2));
        rm1 = fmaxf(rm1, __shfl_xor_sync(0xffffffffu, rm1, 1));
        rm1 = fmaxf(rm1, __shfl_xor_sync(0xffffffffu, rm1, 2));

        float m0n = fmaxf(m0, rm0);
        float m1n = fmaxf(m1, rm1);
        float a0  = __expf(m0 - m0n);
        float a1  = __expf(m1 - m1n);
        m0 = m0n; m1 = m1n;

        float rs0 = 0.f, rs1 = 0.f;
        #pragma unroll
        for (int ni = 0; ni < 16; ni++) {
            float p0 = __expf(sc[ni][0] - m0n);
            float p1 = __expf(sc[ni][1] - m0n);
            float p2 = __expf(sc[ni][2] - m1n);
            float p3 = __expf(sc[ni][3] - m1n);
            rs0 += p0 + p1;
            rs1 += p2 + p3;
            // stage P (tf32) for the PV mma
            unsigned* pr0 = &Ps[(wr + lq    ) * PSTR + ni * 8 + lr * 2];
            unsigned* pr1 = &Ps[(wr + lq + 8) * PSTR + ni * 8 + lr * 2];
            pr0[0] = f2tf32(p0); pr0[1] = f2tf32(p1);
            pr1[0] = f2tf32(p2); pr1[1] = f2tf32(p3);
        }
        rs0 += __shfl_xor_sync(0xffffffffu, rs0, 1);
        rs0 += __shfl_xor_sync(0xffffffffu, rs0, 2);
        rs1 += __shfl_xor_sync(0xffffffffu, rs1, 1);
        rs1 += __shfl_xor_sync(0xffffffffu, rs1, 2);
        l0 = l0 * a0 + rs0;
        l1 = l1 * a1 + rs1;

        // rescale O accumulators
        #pragma unroll
        for (int ni = 0; ni < 10; ni++) {
            oacc[ni][0] *= a0; oacc[ni][1] *= a0;
            oacc[ni][2] *= a1; oacc[ni][3] *= a1;
        }

        __syncwarp();   // Ps is warp-private: order writes vs fragment reads

        // ---- PV: O[16 x 80] += P[16 x 128] @ V[128 x 80] ----
        #pragma unroll
        for (int ks = 0; ks < 16; ks++) {
            unsigned af[4];
            af[0] = Ps[(wr + lq    ) * PSTR + ks * 8 + lr    ];
            af[1] = Ps[(wr + lq + 8) * PSTR + ks * 8 + lr    ];
            af[2] = Ps[(wr + lq    ) * PSTR + ks * 8 + 4 + lr];
            af[3] = Ps[(wr + lq + 8) * PSTR + ks * 8 + 4 + lr];
            #pragma unroll
            for (int ni = 0; ni < 10; ni++) {
                unsigned b0 = Vt[(ni * 8 + lq) * PSTR + ks * 8 + lr    ];
                unsigned b1 = Vt[(ni * 8 + lq) * PSTR + ks * 8 + 4 + lr];
                mma_tf32(oacc[ni], af, b0, b1);
            }
        }
    }

    // ---- epilogue ----
    const float inv0 = 1.0f / l0;
    const float inv1 = 1.0f / l1;
    #pragma unroll
    for (int ni = 0; ni < 10; ni++) {
        int c = ni * 8 + lr * 2;
        float2* p0 = (float2*)(o + (size_t)(b * SEQ + row0) * (NH * HD) + h * HD + c);
        float2* p1 = (float2*)(o + (size_t)(b * SEQ + row1) * (NH * HD) + h * HD + c);
        *p0 = make_float2(oacc[ni][0] * inv0, oacc[ni][1] * inv0);
        *p1 = make_float2(oacc[ni][2] * inv1, oacc[ni][3] * inv1);
    }
}

// ---------------- launch ------------------------------------------------------
extern "C" void kernel_launch(void* const* d_in, const int* in_sizes, int n_in,
                              void* d_out, int out_size)
{
    const float* x    = (const float*)d_in[0];
    const float* cosf = (const float*)d_in[1];
    const float* sinf = (const float*)d_in[2];
    const float* Wq   = (const float*)d_in[3];
    const float* Wk   = (const float*)d_in[4];
    const float* Wv   = (const float*)d_in[5];
    const float* Wo   = (const float*)d_in[6];
    float* out = (float*)d_out;

    float *qb, *kb, *vb, *ob;
    cudaGetSymbolAddress((void**)&qb, g_q);
    cudaGetSymbolAddress((void**)&kb, g_k);
    cudaGetSymbolAddress((void**)&vb, g_v);
    cudaGetSymbolAddress((void**)&ob, g_o);

    // QKV projections (tf32 tensor cores)
    {
        dim3 gq(HIDDEN / GBN, M_TOK / GBM);
        tf32_gemm_kernel<<<gq, 256>>>(x, Wq, qb, M_TOK, NH * HD, HIDDEN);
        dim3 gk((NKV * HD) / GBN, M_TOK / GBM);
        tf32_gemm_kernel<<<gk, 256>>>(x, Wk, kb, M_TOK, NKV * HD, HIDDEN);
        tf32_gemm_kernel<<<gk, 256>>>(x, Wv, vb, M_TOK, NKV * HD, HIDDEN);
    }

    // RoPE on q and k
    {
        int tq = M_TOK * NH * (HD / 2);
        rope_kernel<<<(tq + 255) / 256, 256>>>(qb, cosf, sinf, NH, tq);
        int tk = M_TOK * NKV * (HD / 2);
        rope_kernel<<<(tk + 255) / 256, 256>>>(kb, cosf, sinf, NKV, tk);
    }

    // attention (tf32 tensor cores)
    {
        static const int smem_bytes =
            (128 * QSTR + 128 * QSTR + 80 * PSTR + 128 * PSTR) * 4;  // 195840
        cudaFuncSetAttribute(attn_tc_kernel,
                             cudaFuncAttributeMaxDynamicSharedMemorySize, smem_bytes);
        dim3 ga(SEQ / 128, NH, BATCH);
        attn_tc_kernel<<<ga, 256, smem_bytes>>>(qb, kb, vb, ob);
    }

    // output projection (tf32 tensor cores)
    {
        dim3 go(HIDDEN / GBN, M_TOK / GBM);
        tf32_gemm_kernel<<<go, 256>>>(ob, Wo, out, M_TOK, HIDDEN, HIDDEN);
    }
}

// round 4
// speedup vs baseline: 3.7314x; 1.1399x over previous
#include <cuda_runtime.h>
#include <math.h>

#define HIDDEN 2560
#define NH 32
#define NKV 8
#define HD 80
#define BATCH 2
#define SEQ 2048
#define M_TOK (BATCH * SEQ)   // 4096

// ---------------- scratch (static device globals; no runtime alloc) ----------
__device__ float g_q[M_TOK * NH * HD];    // 4096 x 2560
__device__ float g_k[M_TOK * NKV * HD];   // 4096 x 640
__device__ float g_v[M_TOK * NKV * HD];   // 4096 x 640
__device__ float g_o[M_TOK * NH * HD];    // 4096 x 2560

__device__ __forceinline__ unsigned f2tf32(float x) {
    unsigned y;
    asm("cvt.rna.tf32.f32 %0, %1;" : "=r"(y) : "f"(x));
    return y;
}

__device__ __forceinline__ void mma_tf32(float* c, const unsigned* a,
                                         unsigned b0, unsigned b1) {
    asm volatile(
        "mma.sync.aligned.m16n8k8.row.col.f32.tf32.tf32.f32 "
        "{%0,%1,%2,%3}, {%4,%5,%6,%7}, {%8,%9}, {%0,%1,%2,%3};"
        : "+f"(c[0]), "+f"(c[1]), "+f"(c[2]), "+f"(c[3])
        : "r"(a[0]), "r"(a[1]), "r"(a[2]), "r"(a[3]),
          "r"(b0), "r"(b1));
}

__device__ __forceinline__ void cp_async16(void* smem_ptr, const void* gptr) {
    unsigned saddr = (unsigned)__cvta_generic_to_shared(smem_ptr);
    asm volatile("cp.async.cg.shared.global [%0], [%1], 16;\n"
                 :: "r"(saddr), "l"(gptr));
}
__device__ __forceinline__ void cp_commit() {
    asm volatile("cp.async.commit_group;\n");
}
__device__ __forceinline__ void cp_wait0() {
    asm volatile("cp.async.wait_group 0;\n");
}

// ---------------- pipelined TF32 GEMM, up to 3 output segments ----------------
// C_s[M, N_s] = A[M,K] @ B_s[K, N_s] for segment s chosen by blockIdx.x.
// Block tile 128x128, BK=32, 256 threads (8 warps 4x2), warp tile 32x64.
// 2-stage cp.async double buffer; raw fp32 in smem, cvt->tf32 at fragment load.
#define ASTR 36
#define BSTR 136
#define ASZ (128 * ASTR)            // floats per stage
#define BSZ (32 * BSTR)
#define STG (ASZ + BSZ)             // 8960 floats per stage
#define GEMM_SMEM (2 * STG * 4)     // 71680 bytes

__global__ __launch_bounds__(256) void tf32_gemm3_kernel(
    const float* __restrict__ A,
    const float* __restrict__ B0, float* __restrict__ C0, int N0, int xs0,
    const float* __restrict__ B1, float* __restrict__ C1, int N1, int xs1,
    const float* __restrict__ B2, float* __restrict__ C2, int N2,
    int M, int K)
{
    extern __shared__ float smp[];

    const int bx = blockIdx.x;
    const float* B; float* C; int N; int bxl;
    if (bx < xs0)      { B = B0; C = C0; N = N0; bxl = bx; }
    else if (bx < xs1) { B = B1; C = C1; N = N1; bxl = bx - xs0; }
    else               { B = B2; C = C2; N = N2; bxl = bx - xs1; }

    const int tid  = threadIdx.x;
    const int lane = tid & 31;
    const int warp = tid >> 5;
    const int wm   = (warp & 3) * 32;
    const int wn   = (warp >> 2) * 64;
    const int bm   = blockIdx.y * 128;
    const int bn   = bxl * 128;
    const int lq   = lane >> 2;
    const int lr   = lane & 3;

    // per-thread copy coordinates
    const int arow = tid >> 3;            // 0..31 (x4 = 128 rows over 4 chunks)
    const int ac4  = (tid & 7) * 4;       // 0..28
    const int brow = tid >> 5;            // 0..7  (x4 = 32 rows)
    const int bc4  = (tid & 31) * 4;      // 0..124

    float acc[2][8][4];
    #pragma unroll
    for (int i = 0; i < 2; i++)
        #pragma unroll
        for (int j = 0; j < 8; j++)
            #pragma unroll
            for (int r = 0; r < 4; r++) acc[i][j][r] = 0.f;

    const int T = K / 32;

    // prefetch tile 0 -> stage 0
    {
        float* sA = smp;
        float* sB = smp + ASZ;
        #pragma unroll
        for (int i = 0; i < 4; i++) {
            int row = arow + i * 32;
            cp_async16(&sA[row * ASTR + ac4], A + (size_t)(bm + row) * K + ac4);
        }
        #pragma unroll
        for (int i = 0; i < 4; i++) {
            int row = brow + i * 8;
            cp_async16(&sB[row * BSTR + bc4], B + (size_t)row * N + bn + bc4);
        }
        cp_commit();
    }

    for (int t = 0; t < T; t++) {
        cp_wait0();
        __syncthreads();

        // prefetch tile t+1 into the other stage (overlaps compute below)
        if (t + 1 < T) {
            float* sA = smp + ((t + 1) & 1) * STG;
            float* sB = sA + ASZ;
            int k0 = (t + 1) * 32;
            #pragma unroll
            for (int i = 0; i < 4; i++) {
                int row = arow + i * 32;
                cp_async16(&sA[row * ASTR + ac4], A + (size_t)(bm + row) * K + k0 + ac4);
            }
            #pragma unroll
            for (int i = 0; i < 4; i++) {
                int row = brow + i * 8;
                cp_async16(&sB[row * BSTR + bc4], B + (size_t)(k0 + row) * N + bn + bc4);
            }
        }
        cp_commit();

        // compute on stage t&1
        const float* sA = smp + (t & 1) * STG;
        const float* sB = sA + ASZ;
        #pragma unroll
        for (int ks = 0; ks < 4; ks++) {
            const int kk = ks * 8;
            unsigned af[2][4];
            #pragma unroll
            for (int mi = 0; mi < 2; mi++) {
                int m = wm + mi * 16 + lq;
                af[mi][0] = f2tf32(sA[(m    ) * ASTR + kk + lr    ]);
                af[mi][1] = f2tf32(sA[(m + 8) * ASTR + kk + lr    ]);
                af[mi][2] = f2tf32(sA[(m    ) * ASTR + kk + 4 + lr]);
                af[mi][3] = f2tf32(sA[(m + 8) * ASTR + kk + 4 + lr]);
            }
            unsigned bf[8][2];
            #pragma unroll
            for (int ni = 0; ni < 8; ni++) {
                int n = wn + ni * 8 + lq;
                bf[ni][0] = f2tf32(sB[(kk + lr    ) * BSTR + n]);
                bf[ni][1] = f2tf32(sB[(kk + lr + 4) * BSTR + n]);
            }
            #pragma unroll
            for (int mi = 0; mi < 2; mi++)
                #pragma unroll
                for (int ni = 0; ni < 8; ni++)
                    mma_tf32(acc[mi][ni], af[mi], bf[ni][0], bf[ni][1]);
        }
        __syncthreads();
    }

    #pragma unroll
    for (int mi = 0; mi < 2; mi++) {
        int m = bm + wm + mi * 16 + lq;
        #pragma unroll
        for (int ni = 0; ni < 8; ni++) {
            int n = bn + wn + ni * 8 + lr * 2;
            float2* p0 = (float2*)(C + (size_t)m * N + n);
            float2* p1 = (float2*)(C + (size_t)(m + 8) * N + n);
            *p0 = make_float2(acc[mi][ni][0], acc[mi][ni][1]);
            *p1 = make_float2(acc[mi][ni][2], acc[mi][ni][3]);
        }
    }
}

// ---------------- fused RoPE over q and k -------------------------------------
__global__ void rope_fused_kernel(float* __restrict__ qb, float* __restrict__ kb,
                                  const float* __restrict__ cosf,
                                  const float* __restrict__ sinf,
                                  int tq, int total)
{
    int idx = blockIdx.x * blockDim.x + threadIdx.x;
    if (idx >= total) return;
    float* t; int nheads; int li;
    if (idx < tq) { t = qb; nheads = NH;  li = idx; }
    else          { t = kb; nheads = NKV; li = idx - tq; }

    int i   = li % (HD / 2);
    int h   = (li / (HD / 2)) % nheads;
    int tok = li / ((HD / 2) * nheads);
    int s   = tok % SEQ;

    float* p = t + (size_t)tok * nheads * HD + h * HD;
    float x1 = p[i];
    float x2 = p[i + HD / 2];
    float c1 = cosf[s * HD + i];
    float s1 = sinf[s * HD + i];
    float c2 = cosf[s * HD + i + HD / 2];
    float s2 = sinf[s * HD + i + HD / 2];
    p[i]          = x1 * c1 - x2 * s1;
    p[i + HD / 2] = x2 * c2 + x1 * s2;
}

// ---------------- TF32 tensor-core flash attention (unchanged from R3) --------
#define QSTR 84
#define PSTR 132

__global__ __launch_bounds__(256) void attn_tc_kernel(
    const float* __restrict__ q, const float* __restrict__ k,
    const float* __restrict__ v, float* __restrict__ o)
{
    extern __shared__ unsigned sm[];
    unsigned* Qs = sm;
    unsigned* Ks = Qs + 128 * QSTR;
    unsigned* Vt = Ks + 128 * QSTR;
    unsigned* Ps = Vt + 80 * PSTR;

    const int b    = blockIdx.z;
    const int h    = blockIdx.y;
    const int qt   = blockIdx.x;
    const int kvh  = h >> 2;
    const int tid  = threadIdx.x;
    const int lane = tid & 31;
    const int warp = tid >> 5;
    const int lq   = lane >> 2;
    const int lr   = lane & 3;
    const int wr   = warp * 16;
    const float scale = rsqrtf((float)HD);

    #pragma unroll
    for (int i = 0; i < 10; i++) {
        int f   = tid + i * 256;
        int row = f / 20;
        int c4  = (f % 20) * 4;
        float4 a = *(const float4*)(q + ((size_t)(b * SEQ + qt * 128 + row)) * (NH * HD)
                                      + h * HD + c4);
        Qs[row * QSTR + c4 + 0] = f2tf32(a.x);
        Qs[row * QSTR + c4 + 1] = f2tf32(a.y);
        Qs[row * QSTR + c4 + 2] = f2tf32(a.z);
        Qs[row * QSTR + c4 + 3] = f2tf32(a.w);
    }

    float oacc[10][4];
    #pragma unroll
    for (int i = 0; i < 10; i++)
        #pragma unroll
        for (int j = 0; j < 4; j++) oacc[i][j] = 0.f;
    float m0 = -INFINITY, m1 = -INFINITY;
    float l0 = 0.f, l1 = 0.f;

    const int row0 = qt * 128 + wr + lq;
    const int row1 = row0 + 8;

    for (int kt = 0; kt <= qt; kt++) {
        __syncthreads();
        #pragma unroll
        for (int i = 0; i < 10; i++) {
            int f   = tid + i * 256;
            int row = f / 20;
            int c4  = (f % 20) * 4;
            size_t g = ((size_t)(b * SEQ + kt * 128 + row)) * (NKV * HD) + kvh * HD + c4;
            float4 kk = *(const float4*)(k + g);
            Ks[row * QSTR + c4 + 0] = f2tf32(kk.x);
            Ks[row * QSTR + c4 + 1] = f2tf32(kk.y);
            Ks[row * QSTR + c4 + 2] = f2tf32(kk.z);
            Ks[row * QSTR + c4 + 3] = f2tf32(kk.w);
            float4 vv = *(const float4*)(v + g);
            Vt[(c4 + 0) * PSTR + row] = f2tf32(vv.x);
            Vt[(c4 + 1) * PSTR + row] = f2tf32(vv.y);
            Vt[(c4 + 2) * PSTR + row] = f2tf32(vv.z);
            Vt[(c4 + 3) * PSTR + row] = f2tf32(vv.w);
        }
        __syncthreads();

        float sc[16][4];
        #pragma unroll
        for (int ni = 0; ni < 16; ni++)
            #pragma unroll
            for (int j = 0; j < 4; j++) sc[ni][j] = 0.f;

        #pragma unroll
        for (int ks = 0; ks < 10; ks++) {
            unsigned af[4];
            af[0] = Qs[(wr + lq    ) * QSTR + ks * 8 + lr    ];
            af[1] = Qs[(wr + lq + 8) * QSTR + ks * 8 + lr    ];
            af[2] = Qs[(wr + lq    ) * QSTR + ks * 8 + 4 + lr];
            af[3] = Qs[(wr + lq + 8) * QSTR + ks * 8 + 4 + lr];
            #pragma unroll
            for (int ni = 0; ni < 16; ni++) {
                unsigned b0 = Ks[(ni * 8 + lq) * QSTR + ks * 8 + lr    ];
                unsigned b1 = Ks[(ni * 8 + lq) * QSTR + ks * 8 + 4 + lr];
                mma_tf32(sc[ni], af, b0, b1);
            }
        }

        const bool diag = (kt == qt);
        #pragma unroll
        for (int ni = 0; ni < 16; ni++) {
            int c = kt * 128 + ni * 8 + lr * 2;
            sc[ni][0] = (diag && c     > row0) ? -1e30f : sc[ni][0] * scale;
            sc[ni][1] = (diag && c + 1 > row0) ? -1e30f : sc[ni][1] * scale;
            sc[ni][2] = (diag && c     > row1) ? -1e30f : sc[ni][2] * scale;
            sc[ni][3] = (diag && c + 1 > row1) ? -1e30f : sc[ni][3] * scale;
        }

        float rm0 = -1e30f, rm1 = -1e30f;
        #pragma unroll
        for (int ni = 0; ni < 16; ni++) {
            rm0 = fmaxf(rm0, fmaxf(sc[ni][0], sc[ni][1]));
            rm1 = fmaxf(rm1, fmaxf(sc[ni][2], sc[ni][3]));
        }
        rm0 = fmaxf(rm0, __shfl_xor_sync(0xffffffffu, rm0, 1));
        rm0 = fmaxf(rm0, __shfl_xor_sync(0xffffffffu, rm0, 2));
        rm1 = fmaxf(rm1, __shfl_xor_sync(0xffffffffu, rm1, 1));
        rm1 = fmaxf(rm1, __shfl_xor_sync(0xffffffffu, rm1, 2));

        float m0n = fmaxf(m0, rm0);
        float m1n = fmaxf(m1, rm1);
        float a0  = __expf(m0 - m0n);
        float a1  = __expf(m1 - m1n);
        m0 = m0n; m1 = m1n;

        float rs0 = 0.f, rs1 = 0.f;
        #pragma unroll
        for (int ni = 0; ni < 16; ni++) {
            float p0 = __expf(sc[ni][0] - m0n);
            float p1 = __expf(sc[ni][1] - m0n);
            float p2 = __expf(sc[ni][2] - m1n);
            float p3 = __expf(sc[ni][3] - m1n);
            rs0 += p0 + p1;
            rs1 += p2 + p3;
            unsigned* pr0 = &Ps[(wr + lq    ) * PSTR + ni * 8 + lr * 2];
            unsigned* pr1 = &Ps[(wr + lq + 8) * PSTR + ni * 8 + lr * 2];
            pr0[0] = f2tf32(p0); pr0[1] = f2tf32(p1);
            pr1[0] = f2tf32(p2); pr1[1] = f2tf32(p3);
        }
        rs0 += __shfl_xor_sync(0xffffffffu, rs0, 1);
        rs0 += __shfl_xor_sync(0xffffffffu, rs0, 2);
        rs1 += __shfl_xor_sync(0xffffffffu, rs1, 1);
        rs1 += __shfl_xor_sync(0xffffffffu, rs1, 2);
        l0 = l0 * a0 + rs0;
        l1 = l1 * a1 + rs1;

        #pragma unroll
        for (int ni = 0; ni < 10; ni++) {
            oacc[ni][0] *= a0; oacc[ni][1] *= a0;
            oacc[ni][2] *= a1; oacc[ni][3] *= a1;
        }

        __syncwarp();

        #pragma unroll
        for (int ks = 0; ks < 16; ks++) {
            unsigned af[4];
            af[0] = Ps[(wr + lq    ) * PSTR + ks * 8 + lr    ];
            af[1] = Ps[(wr + lq + 8) * PSTR + ks * 8 + lr    ];
            af[2] = Ps[(wr + lq    ) * PSTR + ks * 8 + 4 + lr];
            af[3] = Ps[(wr + lq + 8) * PSTR + ks * 8 + 4 + lr];
            #pragma unroll
            for (int ni = 0; ni < 10; ni++) {
                unsigned b0 = Vt[(ni * 8 + lq) * PSTR + ks * 8 + lr    ];
                unsigned b1 = Vt[(ni * 8 + lq) * PSTR + ks * 8 + 4 + lr];
                mma_tf32(oacc[ni], af, b0, b1);
            }
        }
    }

    const float inv0 = 1.0f / l0;
    const float inv1 = 1.0f / l1;
    #pragma unroll
    for (int ni = 0; ni < 10; ni++) {
        int c = ni * 8 + lr * 2;
        float2* p0 = (float2*)(o + (size_t)(b * SEQ + row0) * (NH * HD) + h * HD + c);
        float2* p1 = (float2*)(o + (size_t)(b * SEQ + row1) * (NH * HD) + h * HD + c);
        *p0 = make_float2(oacc[ni][0] * inv0, oacc[ni][1] * inv0);
        *p1 = make_float2(oacc[ni][2] * inv1, oacc[ni][3] * inv1);
    }
}

// ---------------- launch ------------------------------------------------------
extern "C" void kernel_launch(void* const* d_in, const int* in_sizes, int n_in,
                              void* d_out, int out_size)
{
    const float* x    = (const float*)d_in[0];
    const float* cosf = (const float*)d_in[1];
    const float* sinf = (const float*)d_in[2];
    const float* Wq   = (const float*)d_in[3];
    const float* Wk   = (const float*)d_in[4];
    const float* Wv   = (const float*)d_in[5];
    const float* Wo   = (const float*)d_in[6];
    float* out = (float*)d_out;

    float *qb, *kb, *vb, *ob;
    cudaGetSymbolAddress((void**)&qb, g_q);
    cudaGetSymbolAddress((void**)&kb, g_k);
    cudaGetSymbolAddress((void**)&vb, g_v);
    cudaGetSymbolAddress((void**)&ob, g_o);

    cudaFuncSetAttribute(tf32_gemm3_kernel,
                         cudaFuncAttributeMaxDynamicSharedMemorySize, GEMM_SMEM);

    // fused Q/K/V projections: segments [0,20)=Q, [20,25)=K, [25,30)=V
    {
        dim3 g(30, M_TOK / 128);
        tf32_gemm3_kernel<<<g, 256, GEMM_SMEM>>>(
            x,
            Wq, qb, NH * HD, 20,
            Wk, kb, NKV * HD, 25,
            Wv, vb, NKV * HD,
            M_TOK, HIDDEN);
    }

    // fused RoPE on q and k
    {
        int tq = M_TOK * NH * (HD / 2);
        int tk = M_TOK * NKV * (HD / 2);
        int tot = tq + tk;
        rope_fused_kernel<<<(tot + 255) / 256, 256>>>(qb, kb, cosf, sinf, tq, tot);
    }

    // attention (tf32 tensor cores)
    {
        static const int smem_bytes =
            (128 * QSTR + 128 * QSTR + 80 * PSTR + 128 * PSTR) * 4;
        cudaFuncSetAttribute(attn_tc_kernel,
                             cudaFuncAttributeMaxDynamicSharedMemorySize, smem_bytes);
        dim3 ga(SEQ / 128, NH, BATCH);
        attn_tc_kernel<<<ga, 256, smem_bytes>>>(qb, kb, vb, ob);
    }

    // output projection
    {
        dim3 go(HIDDEN / 128, M_TOK / 128);
        tf32_gemm3_kernel<<<go, 256, GEMM_SMEM>>>(
            ob,
            Wo, out, HIDDEN, 20,
            Wo, out, HIDDEN, 20,
            Wo, out, HIDDEN,
            M_TOK, HIDDEN);
    }
}

// round 5
// speedup vs baseline: 4.0000x; 1.0720x over previous
#include <cuda_runtime.h>
#include <math.h>

#define HIDDEN 2560
#define NH 32
#define NKV 8
#define HD 80
#define BATCH 2
#define SEQ 2048
#define M_TOK (BATCH * SEQ)   // 4096

// ---------------- scratch (static device globals; no runtime alloc) ----------
__device__ float g_q[M_TOK * NH * HD];        // 4096 x 2560
__device__ float g_k[M_TOK * NKV * HD];       // 4096 x 640
__device__ float g_v[M_TOK * NKV * HD];       // 4096 x 640
__device__ float g_o[M_TOK * NH * HD];        // 4096 x 2560 (tf32-rounded bits)
__device__ float g_xc[M_TOK * HIDDEN];        // tf32-rounded x
__device__ float g_wqc[HIDDEN * NH * HD];     // tf32-rounded weights
__device__ float g_wkc[HIDDEN * NKV * HD];
__device__ float g_wvc[HIDDEN * NKV * HD];
__device__ float g_woc[NH * HD * HIDDEN];

__device__ __forceinline__ unsigned f2tf32(float x) {
    unsigned y;
    asm("cvt.rna.tf32.f32 %0, %1;" : "=r"(y) : "f"(x));
    return y;
}

__device__ __forceinline__ void mma_tf32(float* c, const unsigned* a,
                                         unsigned b0, unsigned b1) {
    asm volatile(
        "mma.sync.aligned.m16n8k8.row.col.f32.tf32.tf32.f32 "
        "{%0,%1,%2,%3}, {%4,%5,%6,%7}, {%8,%9}, {%0,%1,%2,%3};"
        : "+f"(c[0]), "+f"(c[1]), "+f"(c[2]), "+f"(c[3])
        : "r"(a[0]), "r"(a[1]), "r"(a[2]), "r"(a[3]),
          "r"(b0), "r"(b1));
}

__device__ __forceinline__ void cp_async16(void* smem_ptr, const void* gptr) {
    unsigned saddr = (unsigned)__cvta_generic_to_shared(smem_ptr);
    asm volatile("cp.async.cg.shared.global [%0], [%1], 16;\n"
                 :: "r"(saddr), "l"(gptr));
}
__device__ __forceinline__ void cp_commit() {
    asm volatile("cp.async.commit_group;\n");
}
__device__ __forceinline__ void cp_wait0() {
    asm volatile("cp.async.wait_group 0;\n");
}

// ---------------- elementwise tf32 rounding (float4 vectorized) ---------------
__global__ void cvt_tf32_kernel(const float4* __restrict__ in,
                                float4* __restrict__ out, int n4)
{
    int i = blockIdx.x * blockDim.x + threadIdx.x;
    if (i >= n4) return;
    float4 a = in[i];
    a.x = __uint_as_float(f2tf32(a.x));
    a.y = __uint_as_float(f2tf32(a.y));
    a.z = __uint_as_float(f2tf32(a.z));
    a.w = __uint_as_float(f2tf32(a.w));
    out[i] = a;
}

// ---------------- pipelined TF32 GEMM, up to 3 output segments ----------------
// Operands are PRE-ROUNDED to tf32 bit patterns; inner loop has zero CVTs.
#define ASTR 36
#define BSTR 136
#define ASZ (128 * ASTR)
#define BSZ (32 * BSTR)
#define STG (ASZ + BSZ)
#define GEMM_SMEM (2 * STG * 4)     // 71680 bytes

__global__ __launch_bounds__(256) void tf32_gemm3_kernel(
    const float* __restrict__ A,
    const float* __restrict__ B0, float* __restrict__ C0, int N0, int xs0,
    const float* __restrict__ B1, float* __restrict__ C1, int N1, int xs1,
    const float* __restrict__ B2, float* __restrict__ C2, int N2,
    int M, int K)
{
    extern __shared__ float smp[];

    const int bx = blockIdx.x;
    const float* B; float* C; int N; int bxl;
    if (bx < xs0)      { B = B0; C = C0; N = N0; bxl = bx; }
    else if (bx < xs1) { B = B1; C = C1; N = N1; bxl = bx - xs0; }
    else               { B = B2; C = C2; N = N2; bxl = bx - xs1; }

    const int tid  = threadIdx.x;
    const int lane = tid & 31;
    const int warp = tid >> 5;
    const int wm   = (warp & 3) * 32;
    const int wn   = (warp >> 2) * 64;
    const int bm   = blockIdx.y * 128;
    const int bn   = bxl * 128;
    const int lq   = lane >> 2;
    const int lr   = lane & 3;

    const int arow = tid >> 3;
    const int ac4  = (tid & 7) * 4;
    const int brow = tid >> 5;
    const int bc4  = (tid & 31) * 4;

    float acc[2][8][4];
    #pragma unroll
    for (int i = 0; i < 2; i++)
        #pragma unroll
        for (int j = 0; j < 8; j++)
            #pragma unroll
            for (int r = 0; r < 4; r++) acc[i][j][r] = 0.f;

    const int T = K / 32;

    {
        float* sA = smp;
        float* sB = smp + ASZ;
        #pragma unroll
        for (int i = 0; i < 4; i++) {
            int row = arow + i * 32;
            cp_async16(&sA[row * ASTR + ac4], A + (size_t)(bm + row) * K + ac4);
        }
        #pragma unroll
        for (int i = 0; i < 4; i++) {
            int row = brow + i * 8;
            cp_async16(&sB[row * BSTR + bc4], B + (size_t)row * N + bn + bc4);
        }
        cp_commit();
    }

    for (int t = 0; t < T; t++) {
        cp_wait0();
        __syncthreads();

        if (t + 1 < T) {
            float* sA = smp + ((t + 1) & 1) * STG;
            float* sB = sA + ASZ;
            int k0 = (t + 1) * 32;
            #pragma unroll
            for (int i = 0; i < 4; i++) {
                int row = arow + i * 32;
                cp_async16(&sA[row * ASTR + ac4], A + (size_t)(bm + row) * K + k0 + ac4);
            }
            #pragma unroll
            for (int i = 0; i < 4; i++) {
                int row = brow + i * 8;
                cp_async16(&sB[row * BSTR + bc4], B + (size_t)(k0 + row) * N + bn + bc4);
            }
        }
        cp_commit();

        const float* sA = smp + (t & 1) * STG;
        const float* sB = sA + ASZ;
        #pragma unroll
        for (int ks = 0; ks < 4; ks++) {
            const int kk = ks * 8;
            unsigned af[2][4];
            #pragma unroll
            for (int mi = 0; mi < 2; mi++) {
                int m = wm + mi * 16 + lq;
                af[mi][0] = __float_as_uint(sA[(m    ) * ASTR + kk + lr    ]);
                af[mi][1] = __float_as_uint(sA[(m + 8) * ASTR + kk + lr    ]);
                af[mi][2] = __float_as_uint(sA[(m    ) * ASTR + kk + 4 + lr]);
                af[mi][3] = __float_as_uint(sA[(m + 8) * ASTR + kk + 4 + lr]);
            }
            unsigned bf[8][2];
            #pragma unroll
            for (int ni = 0; ni < 8; ni++) {
                int n = wn + ni * 8 + lq;
                bf[ni][0] = __float_as_uint(sB[(kk + lr    ) * BSTR + n]);
                bf[ni][1] = __float_as_uint(sB[(kk + lr + 4) * BSTR + n]);
            }
            #pragma unroll
            for (int mi = 0; mi < 2; mi++)
                #pragma unroll
                for (int ni = 0; ni < 8; ni++)
                    mma_tf32(acc[mi][ni], af[mi], bf[ni][0], bf[ni][1]);
        }
        __syncthreads();
    }

    #pragma unroll
    for (int mi = 0; mi < 2; mi++) {
        int m = bm + wm + mi * 16 + lq;
        #pragma unroll
        for (int ni = 0; ni < 8; ni++) {
            int n = bn + wn + ni * 8 + lr * 2;
            float2* p0 = (float2*)(C + (size_t)m * N + n);
            float2* p1 = (float2*)(C + (size_t)(m + 8) * N + n);
            *p0 = make_float2(acc[mi][ni][0], acc[mi][ni][1]);
            *p1 = make_float2(acc[mi][ni][2], acc[mi][ni][3]);
        }
    }
}

// ---------------- fused RoPE over q and k -------------------------------------
__global__ void rope_fused_kernel(float* __restrict__ qb, float* __restrict__ kb,
                                  const float* __restrict__ cosf,
                                  const float* __restrict__ sinf,
                                  int tq, int total)
{
    int idx = blockIdx.x * blockDim.x + threadIdx.x;
    if (idx >= total) return;
    float* t; int nheads; int li;
    if (idx < tq) { t = qb; nheads = NH;  li = idx; }
    else          { t = kb; nheads = NKV; li = idx - tq; }

    int i   = li % (HD / 2);
    int h   = (li / (HD / 2)) % nheads;
    int tok = li / ((HD / 2) * nheads);
    int s   = tok % SEQ;

    float* p = t + (size_t)tok * nheads * HD + h * HD;
    float x1 = p[i];
    float x2 = p[i + HD / 2];
    float c1 = cosf[s * HD + i];
    float s1 = sinf[s * HD + i];
    float c2 = cosf[s * HD + i + HD / 2];
    float s2 = sinf[s * HD + i + HD / 2];
    p[i]          = x1 * c1 - x2 * s1;
    p[i + HD / 2] = x2 * c2 + x1 * s2;
}

// ---------------- TF32 tensor-core flash attention ----------------------------
// Epilogue writes tf32-rounded output so the Wo GEMM needs no conversion.
#define QSTR 84
#define PSTR 132

__global__ __launch_bounds__(256) void attn_tc_kernel(
    const float* __restrict__ q, const float* __restrict__ k,
    const float* __restrict__ v, float* __restrict__ o)
{
    extern __shared__ unsigned sm[];
    unsigned* Qs = sm;
    unsigned* Ks = Qs + 128 * QSTR;
    unsigned* Vt = Ks + 128 * QSTR;
    unsigned* Ps = Vt + 80 * PSTR;

    const int b    = blockIdx.z;
    const int h    = blockIdx.y;
    const int qt   = blockIdx.x;
    const int kvh  = h >> 2;
    const int tid  = threadIdx.x;
    const int lane = tid & 31;
    const int warp = tid >> 5;
    const int lq   = lane >> 2;
    const int lr   = lane & 3;
    const int wr   = warp * 16;
    const float scale = rsqrtf((float)HD);

    #pragma unroll
    for (int i = 0; i < 10; i++) {
        int f   = tid + i * 256;
        int row = f / 20;
        int c4  = (f % 20) * 4;
        float4 a = *(const float4*)(q + ((size_t)(b * SEQ + qt * 128 + row)) * (NH * HD)
                                      + h * HD + c4);
        Qs[row * QSTR + c4 + 0] = f2tf32(a.x);
        Qs[row * QSTR + c4 + 1] = f2tf32(a.y);
        Qs[row * QSTR + c4 + 2] = f2tf32(a.z);
        Qs[row * QSTR + c4 + 3] = f2tf32(a.w);
    }

    float oacc[10][4];
    #pragma unroll
    for (int i = 0; i < 10; i++)
        #pragma unroll
        for (int j = 0; j < 4; j++) oacc[i][j] = 0.f;
    float m0 = -INFINITY, m1 = -INFINITY;
    float l0 = 0.f, l1 = 0.f;

    const int row0 = qt * 128 + wr + lq;
    const int row1 = row0 + 8;

    for (int kt = 0; kt <= qt; kt++) {
        __syncthreads();
        #pragma unroll
        for (int i = 0; i < 10; i++) {
            int f   = tid + i * 256;
            int row = f / 20;
            int c4  = (f % 20) * 4;
            size_t g = ((size_t)(b * SEQ + kt * 128 + row)) * (NKV * HD) + kvh * HD + c4;
            float4 kk = *(const float4*)(k + g);
            Ks[row * QSTR + c4 + 0] = f2tf32(kk.x);
            Ks[row * QSTR + c4 + 1] = f2tf32(kk.y);
            Ks[row * QSTR + c4 + 2] = f2tf32(kk.z);
            Ks[row * QSTR + c4 + 3] = f2tf32(kk.w);
            float4 vv = *(const float4*)(v + g);
            Vt[(c4 + 0) * PSTR + row] = f2tf32(vv.x);
            Vt[(c4 + 1) * PSTR + row] = f2tf32(vv.y);
            Vt[(c4 + 2) * PSTR + row] = f2tf32(vv.z);
            Vt[(c4 + 3) * PSTR + row] = f2tf32(vv.w);
        }
        __syncthreads();

        float sc[16][4];
        #pragma unroll
        for (int ni = 0; ni < 16; ni++)
            #pragma unroll
            for (int j = 0; j < 4; j++) sc[ni][j] = 0.f;

        #pragma unroll
        for (int ks = 0; ks < 10; ks++) {
            unsigned af[4];
            af[0] = Qs[(wr + lq    ) * QSTR + ks * 8 + lr    ];
            af[1] = Qs[(wr + lq + 8) * QSTR + ks * 8 + lr    ];
            af[2] = Qs[(wr + lq    ) * QSTR + ks * 8 + 4 + lr];
            af[3] = Qs[(wr + lq + 8) * QSTR + ks * 8 + 4 + lr];
            #pragma unroll
            for (int ni = 0; ni < 16; ni++) {
                unsigned b0 = Ks[(ni * 8 + lq) * QSTR + ks * 8 + lr    ];
                unsigned b1 = Ks[(ni * 8 + lq) * QSTR + ks * 8 + 4 + lr];
                mma_tf32(sc[ni], af, b0, b1);
            }
        }

        const bool diag = (kt == qt);
        #pragma unroll
        for (int ni = 0; ni < 16; ni++) {
            int c = kt * 128 + ni * 8 + lr * 2;
            sc[ni][0] = (diag && c     > row0) ? -1e30f : sc[ni][0] * scale;
            sc[ni][1] = (diag && c + 1 > row0) ? -1e30f : sc[ni][1] * scale;
            sc[ni][2] = (diag && c     > row1) ? -1e30f : sc[ni][2] * scale;
            sc[ni][3] = (diag && c + 1 > row1) ? -1e30f : sc[ni][3] * scale;
        }

        float rm0 = -1e30f, rm1 = -1e30f;
        #pragma unroll
        for (int ni = 0; ni < 16; ni++) {
            rm0 = fmaxf(rm0, fmaxf(sc[ni][0], sc[ni][1]));
            rm1 = fmaxf(rm1, fmaxf(sc[ni][2], sc[ni][3]));
        }
        rm0 = fmaxf(rm0, __shfl_xor_sync(0xffffffffu, rm0, 1));
        rm0 = fmaxf(rm0, __shfl_xor_sync(0xffffffffu, rm0, 2));
        rm1 = fmaxf(rm1, __shfl_xor_sync(0xffffffffu, rm1, 1));
        rm1 = fmaxf(rm1, __shfl_xor_sync(0xffffffffu, rm1, 2));

        float m0n = fmaxf(m0, rm0);
        float m1n = fmaxf(m1, rm1);
        float a0  = __expf(m0 - m0n);
        float a1  = __expf(m1 - m1n);
        m0 = m0n; m1 = m1n;

        float rs0 = 0.f, rs1 = 0.f;
        #pragma unroll
        for (int ni = 0; ni < 16; ni++) {
            float p0 = __expf(sc[ni][0] - m0n);
            float p1 = __expf(sc[ni][1] - m0n);
            float p2 = __expf(sc[ni][2] - m1n);
            float p3 = __expf(sc[ni][3] - m1n);
            rs0 += p0 + p1;
            rs1 += p2 + p3;
            unsigned* pr0 = &Ps[(wr + lq    ) * PSTR + ni * 8 + lr * 2];
            unsigned* pr1 = &Ps[(wr + lq + 8) * PSTR + ni * 8 + lr * 2];
            pr0[0] = f2tf32(p0); pr0[1] = f2tf32(p1);
            pr1[0] = f2tf32(p2); pr1[1] = f2tf32(p3);
        }
        rs0 += __shfl_xor_sync(0xffffffffu, rs0, 1);
        rs0 += __shfl_xor_sync(0xffffffffu, rs0, 2);
        rs1 += __shfl_xor_sync(0xffffffffu, rs1, 1);
        rs1 += __shfl_xor_sync(0xffffffffu, rs1, 2);
        l0 = l0 * a0 + rs0;
        l1 = l1 * a1 + rs1;

        #pragma unroll
        for (int ni = 0; ni < 10; ni++) {
            oacc[ni][0] *= a0; oacc[ni][1] *= a0;
            oacc[ni][2] *= a1; oacc[ni][3] *= a1;
        }

        __syncwarp();

        #pragma unroll
        for (int ks = 0; ks < 16; ks++) {
            unsigned af[4];
            af[0] = Ps[(wr + lq    ) * PSTR + ks * 8 + lr    ];
            af[1] = Ps[(wr + lq + 8) * PSTR + ks * 8 + lr    ];
            af[2] = Ps[(wr + lq    ) * PSTR + ks * 8 + 4 + lr];
            af[3] = Ps[(wr + lq + 8) * PSTR + ks * 8 + 4 + lr];
            #pragma unroll
            for (int ni = 0; ni < 10; ni++) {
                unsigned b0 = Vt[(ni * 8 + lq) * PSTR + ks * 8 + lr    ];
                unsigned b1 = Vt[(ni * 8 + lq) * PSTR + ks * 8 + 4 + lr];
                mma_tf32(oacc[ni], af, b0, b1);
            }
        }
    }

    // epilogue: tf32-rounded so Wo GEMM can consume directly
    const float inv0 = 1.0f / l0;
    const float inv1 = 1.0f / l1;
    #pragma unroll
    for (int ni = 0; ni < 10; ni++) {
        int c = ni * 8 + lr * 2;
        float2* p0 = (float2*)(o + (size_t)(b * SEQ + row0) * (NH * HD) + h * HD + c);
        float2* p1 = (float2*)(o + (size_t)(b * SEQ + row1) * (NH * HD) + h * HD + c);
        *p0 = make_float2(__uint_as_float(f2tf32(oacc[ni][0] * inv0)),
                          __uint_as_float(f2tf32(oacc[ni][1] * inv0)));
        *p1 = make_float2(__uint_as_float(f2tf32(oacc[ni][2] * inv1)),
                          __uint_as_float(f2tf32(oacc[ni][3] * inv1)));
    }
}

// ---------------- launch ------------------------------------------------------
extern "C" void kernel_launch(void* const* d_in, const int* in_sizes, int n_in,
                              void* d_out, int out_size)
{
    const float* x    = (const float*)d_in[0];
    const float* cosf = (const float*)d_in[1];
    const float* sinf = (const float*)d_in[2];
    const float* Wq   = (const float*)d_in[3];
    const float* Wk   = (const float*)d_in[4];
    const float* Wv   = (const float*)d_in[5];
    const float* Wo   = (const float*)d_in[6];
    float* out = (float*)d_out;

    float *qb, *kb, *vb, *ob, *xc, *wqc, *wkc, *wvc, *woc;
    cudaGetSymbolAddress((void**)&qb, g_q);
    cudaGetSymbolAddress((void**)&kb, g_k);
    cudaGetSymbolAddress((void**)&vb, g_v);
    cudaGetSymbolAddress((void**)&ob, g_o);
    cudaGetSymbolAddress((void**)&xc, g_xc);
    cudaGetSymbolAddress((void**)&wqc, g_wqc);
    cudaGetSymbolAddress((void**)&wkc, g_wkc);
    cudaGetSymbolAddress((void**)&wvc, g_wvc);
    cudaGetSymbolAddress((void**)&woc, g_woc);

    // pre-round operands to tf32
    {
        int n;
        n = M_TOK * HIDDEN / 4;
        cvt_tf32_kernel<<<(n + 255) / 256, 256>>>((const float4*)x, (float4*)xc, n);
        n = HIDDEN * NH * HD / 4;
        cvt_tf32_kernel<<<(n + 255) / 256, 256>>>((const float4*)Wq, (float4*)wqc, n);
        n = HIDDEN * NKV * HD / 4;
        cvt_tf32_kernel<<<(n + 255) / 256, 256>>>((const float4*)Wk, (float4*)wkc, n);
        cvt_tf32_kernel<<<(n + 255) / 256, 256>>>((const float4*)Wv, (float4*)wvc, n);
        n = NH * HD * HIDDEN / 4;
        cvt_tf32_kernel<<<(n + 255) / 256, 256>>>((const float4*)Wo, (float4*)woc, n);
    }

    cudaFuncSetAttribute(tf32_gemm3_kernel,
                         cudaFuncAttributeMaxDynamicSharedMemorySize, GEMM_SMEM);

    // fused Q/K/V projections
    {
        dim3 g(30, M_TOK / 128);
        tf32_gemm3_kernel<<<g, 256, GEMM_SMEM>>>(
            xc,
            wqc, qb, NH * HD, 20,
            wkc, kb, NKV * HD, 25,
            wvc, vb, NKV * HD,
            M_TOK, HIDDEN);
    }

    // fused RoPE
    {
        int tq = M_TOK * NH * (HD / 2);
        int tk = M_TOK * NKV * (HD / 2);
        int tot = tq + tk;
        rope_fused_kernel<<<(tot + 255) / 256, 256>>>(qb, kb, cosf, sinf, tq, tot);
    }

    // attention
    {
        static const int smem_bytes =
            (128 * QSTR + 128 * QSTR + 80 * PSTR + 128 * PSTR) * 4;
        cudaFuncSetAttribute(attn_tc_kernel,
                             cudaFuncAttributeMaxDynamicSharedMemorySize, smem_bytes);
        dim3 ga(SEQ / 128, NH, BATCH);
        attn_tc_kernel<<<ga, 256, smem_bytes>>>(qb, kb, vb, ob);
    }

    // output projection
    {
        dim3 go(HIDDEN / 128, M_TOK / 128);
        tf32_gemm3_kernel<<<go, 256, GEMM_SMEM>>>(
            ob,
            woc, out, HIDDEN, 20,
            woc, out, HIDDEN, 20,
            woc, out, HIDDEN,
            M_TOK, HIDDEN);
    }
}